// round 1
// baseline (speedup 1.0000x reference)
#include <cuda_runtime.h>
#include <cuda_bf16.h>
#include <cstdint>

// Problem constants (fixed for this dataset)
#define NMAX 100000
#define DIN  256
#define HEADS 4
#define OUTD 32
#define JW   128      // HEADS*OUTD
#define ALPHA_LR 0.2f

// -------- scratch (static device globals; no runtime allocation) --------
__device__ float g_fts[(size_t)NMAX * JW];     // [N][128] per-head features, head-major cols
__device__ float g_f1[(size_t)NMAX * HEADS];   // [N][4]
__device__ float g_f2[(size_t)NMAX * HEADS];   // [N][4]
__device__ float g_denom[(size_t)NMAX * HEADS];// [N][4]

// vector reduction to global (sm_90+)
__device__ __forceinline__ void red_add_v4(float* addr, float4 v) {
    asm volatile("red.global.add.v4.f32 [%0], {%1, %2, %3, %4};"
                 :: "l"(addr), "f"(v.x), "f"(v.y), "f"(v.z), "f"(v.w)
                 : "memory");
}

// ------------------------------------------------------------------
// Kernel 1: fts[n][h*32+o] = sum_d x[n][d] * W[h][d][o]
// BM=64 rows, BN=128 (full width), BK=32, 256 threads, 8x4 microtile.
// ------------------------------------------------------------------
#define BM 64
#define BK 32
__global__ __launch_bounds__(256) void gemm_fts(const float* __restrict__ x,
                                                const float* __restrict__ W,
                                                int N) {
    __shared__ float As[BM][BK];     // 8 KB
    __shared__ float Bs[BK][JW];     // 16 KB

    const int tid = threadIdx.x;
    const int tx  = tid & 31;   // column group (4 cols each)
    const int ty  = tid >> 5;   // row group (8 rows each)
    const int row0 = blockIdx.x * BM;

    float acc[8][4];
    #pragma unroll
    for (int i = 0; i < 8; i++)
        #pragma unroll
        for (int c = 0; c < 4; c++) acc[i][c] = 0.f;

    for (int k0 = 0; k0 < DIN; k0 += BK) {
        // load A tile: 64x32 = 512 float4, 2 per thread
        #pragma unroll
        for (int i = 0; i < 2; i++) {
            int f  = tid + i * 256;
            int r  = f >> 3;
            int kq = f & 7;
            float4 v = make_float4(0.f, 0.f, 0.f, 0.f);
            int gr = row0 + r;
            if (gr < N)
                v = *(const float4*)(x + (size_t)gr * DIN + k0 + kq * 4);
            *(float4*)(&As[r][kq * 4]) = v;
        }
        // load B tile: 32x128 = 1024 float4, 4 per thread
        // Bs[k][j] = W[h][k0+k][o], j = h*32+o
        #pragma unroll
        for (int i = 0; i < 4; i++) {
            int f  = tid + i * 256;
            int k  = f >> 5;
            int jq = f & 31;          // float4 index within row
            int h  = jq >> 3;
            int o  = (jq & 7) * 4;
            float4 v = *(const float4*)(W + (size_t)h * (DIN * OUTD) + (size_t)(k0 + k) * OUTD + o);
            *(float4*)(&Bs[k][jq * 4]) = v;
        }
        __syncthreads();

        #pragma unroll
        for (int k = 0; k < BK; k++) {
            float4 bv = *(float4*)(&Bs[k][tx * 4]);
            float a[8];
            #pragma unroll
            for (int i = 0; i < 8; i++) a[i] = As[ty * 8 + i][k];
            #pragma unroll
            for (int i = 0; i < 8; i++) {
                acc[i][0] = fmaf(a[i], bv.x, acc[i][0]);
                acc[i][1] = fmaf(a[i], bv.y, acc[i][1]);
                acc[i][2] = fmaf(a[i], bv.z, acc[i][2]);
                acc[i][3] = fmaf(a[i], bv.w, acc[i][3]);
            }
        }
        __syncthreads();
    }

    #pragma unroll
    for (int i = 0; i < 8; i++) {
        int gr = row0 + ty * 8 + i;
        if (gr < N) {
            float4 v = make_float4(acc[i][0], acc[i][1], acc[i][2], acc[i][3]);
            *(float4*)(g_fts + (size_t)gr * JW + tx * 4) = v;
        }
    }
}

// ------------------------------------------------------------------
// Kernel 2: per-node attention scalars f1,f2; also zero denom.
// One warp per node. Lane l: head h=l>>3, quarter q=l&7.
// ------------------------------------------------------------------
__global__ __launch_bounds__(256) void node_scalars(const float* __restrict__ a1,
                                                    const float* __restrict__ b1,
                                                    const float* __restrict__ a2,
                                                    const float* __restrict__ b2,
                                                    int N) {
    int gw = (blockIdx.x * blockDim.x + threadIdx.x) >> 5;
    if (gw >= N) return;
    int l = threadIdx.x & 31;
    int h = l >> 3;
    int q = l & 7;

    float4 ft  = *(const float4*)(g_fts + (size_t)gw * JW + l * 4);
    float4 a1v = *(const float4*)(a1 + h * OUTD + q * 4);
    float4 a2v = *(const float4*)(a2 + h * OUTD + q * 4);

    float p1 = ft.x * a1v.x + ft.y * a1v.y + ft.z * a1v.z + ft.w * a1v.w;
    float p2 = ft.x * a2v.x + ft.y * a2v.y + ft.z * a2v.z + ft.w * a2v.w;
    #pragma unroll
    for (int m = 4; m >= 1; m >>= 1) {
        p1 += __shfl_xor_sync(0xFFFFFFFFu, p1, m);
        p2 += __shfl_xor_sync(0xFFFFFFFFu, p2, m);
    }
    if (q == 0) {
        g_f1[(size_t)gw * HEADS + h] = p1 + b1[h];
        g_f2[(size_t)gw * HEADS + h] = p2 + b2[h];
    }
    if (l < HEADS) g_denom[(size_t)gw * HEADS + l] = 0.f;
}

// ------------------------------------------------------------------
// Kernel 3: softmax denominators (no max-pass needed; exp args < ~9).
// One thread per edge, float4 vector reduction over 4 heads.
// ------------------------------------------------------------------
__device__ __forceinline__ float lrelu_exp(float s) {
    return __expf(fmaxf(ALPHA_LR * s, s));
}

__global__ __launch_bounds__(256) void edge_denom(const int* __restrict__ er,
                                                  const int* __restrict__ ec,
                                                  int E) {
    int e = blockIdx.x * blockDim.x + threadIdx.x;
    if (e >= E) return;
    int r = __ldg(er + e);
    int c = __ldg(ec + e);
    float4 f1v = *(const float4*)(g_f1 + (size_t)r * HEADS);
    float4 f2v = *(const float4*)(g_f2 + (size_t)c * HEADS);
    float4 w;
    w.x = lrelu_exp(f1v.x + f2v.x);
    w.y = lrelu_exp(f1v.y + f2v.y);
    w.z = lrelu_exp(f1v.z + f2v.z);
    w.w = lrelu_exp(f1v.w + f2v.w);
    red_add_v4(g_denom + (size_t)r * HEADS, w);
}

// ------------------------------------------------------------------
// Kernel 4: aggregation. One warp per edge; lane l handles float4
// chunk l of the 128-wide message; head = l>>3. Vector red into d_out.
// ------------------------------------------------------------------
__global__ __launch_bounds__(256) void edge_agg(const int* __restrict__ er,
                                                const int* __restrict__ ec,
                                                float* __restrict__ out,
                                                int E) {
    int gw = (blockIdx.x * blockDim.x + threadIdx.x) >> 5;
    if (gw >= E) return;
    int l = threadIdx.x & 31;
    int h = l >> 3;

    int r = __ldg(er + gw);
    int c = __ldg(ec + gw);

    float s    = g_f1[(size_t)r * HEADS + h] + g_f2[(size_t)c * HEADS + h];
    float coef = lrelu_exp(s) / g_denom[(size_t)r * HEADS + h];

    float4 ft = *(const float4*)(g_fts + (size_t)c * JW + l * 4);
    float4 m  = make_float4(ft.x * coef, ft.y * coef, ft.z * coef, ft.w * coef);
    red_add_v4(out + (size_t)r * JW + l * 4, m);
}

// ------------------------------------------------------------------
// Kernel 5: in-place ELU on d_out.
// ------------------------------------------------------------------
__global__ __launch_bounds__(256) void elu_inplace(float* __restrict__ out, int n) {
    int i = blockIdx.x * blockDim.x + threadIdx.x;
    if (i < n) {
        float v = out[i];
        out[i] = v > 0.f ? v : expm1f(v);
    }
}

// ------------------------------------------------------------------
extern "C" void kernel_launch(void* const* d_in, const int* in_sizes, int n_in,
                              void* d_out, int out_size) {
    const float* x  = (const float*)d_in[0];
    const float* W  = (const float*)d_in[1];
    const float* a1 = (const float*)d_in[2];
    const float* b1 = (const float*)d_in[3];
    const float* a2 = (const float*)d_in[4];
    const float* b2 = (const float*)d_in[5];
    const int* er   = (const int*)d_in[6];
    const int* ec   = (const int*)d_in[7];
    float* out      = (float*)d_out;

    const int N = in_sizes[0] / DIN;
    const int E = in_sizes[6];

    // output accumulates via atomics -> must start at zero
    cudaMemsetAsync(d_out, 0, (size_t)out_size * sizeof(float));

    gemm_fts<<<(N + BM - 1) / BM, 256>>>(x, W, N);

    node_scalars<<<((size_t)N * 32 + 255) / 256, 256>>>(a1, b1, a2, b2, N);

    edge_denom<<<(E + 255) / 256, 256>>>(er, ec, E);

    edge_agg<<<((size_t)E * 32 + 255) / 256, 256>>>(er, ec, out, E);

    elu_inplace<<<(out_size + 255) / 256, 256>>>(out, out_size);
}

// round 2
// speedup vs baseline: 1.3241x; 1.3241x over previous
#include <cuda_runtime.h>
#include <cuda_bf16.h>
#include <cstdint>

// Problem constants (fixed for this dataset)
#define NMAX 100000
#define EMAX 1600000
#define DIN  256
#define HEADS 4
#define OUTD 32
#define JW   128      // HEADS*OUTD
#define ALPHA_LR 0.2f

// -------- scratch (static device globals; no runtime allocation) --------
__device__ float  g_fts[(size_t)NMAX * JW];    // [N][128] per-head features
__device__ float2 g_r2[(size_t)NMAX * HEADS];  // row side: {exp(f1), exp(0.2*f1)}
__device__ float2 g_c2[(size_t)NMAX * HEADS];  // col side: {exp(f2), exp(0.2*f2)}
__device__ int    g_cnt[NMAX];                 // per-row edge counts (degree)
__device__ int    g_base[NMAX];                // CSR row starts
__device__ int    g_cur[NMAX];                 // scatter cursors
__device__ int    g_part[1024];                // block partial sums for scan
__device__ int    g_scol[EMAX];                // binned column indices

// ------------------------------------------------------------------
// Kernel 1: fts[n][h*32+o] = sum_d x[n][d] * W[h][d][o]
// 128x128 tile, BK=16, 256 threads, 8x8 microtile.
// ------------------------------------------------------------------
#define GBM 128
#define GBK 16
__global__ __launch_bounds__(256) void gemm_fts(const float* __restrict__ x,
                                                const float* __restrict__ W,
                                                int N) {
    __shared__ float As[GBM][GBK + 1];   // padded: conflict-free column reads
    __shared__ float Bs[GBK][JW];

    const int tid = threadIdx.x;
    const int tx  = tid & 15;    // cols tx*8 .. tx*8+7
    const int ty  = tid >> 4;    // rows ty*8 .. ty*8+7
    const int row0 = blockIdx.x * GBM;

    float acc[8][8];
    #pragma unroll
    for (int i = 0; i < 8; i++)
        #pragma unroll
        for (int j = 0; j < 8; j++) acc[i][j] = 0.f;

    for (int k0 = 0; k0 < DIN; k0 += GBK) {
        // A tile: 128 rows x 16 k  = 512 float4, 2 per thread
        #pragma unroll
        for (int i = 0; i < 2; i++) {
            int f  = tid + i * 256;
            int r  = f >> 2;
            int kq = f & 3;
            float4 v = make_float4(0.f, 0.f, 0.f, 0.f);
            int gr = row0 + r;
            if (gr < N)
                v = *(const float4*)(x + (size_t)gr * DIN + k0 + kq * 4);
            As[r][kq * 4 + 0] = v.x;
            As[r][kq * 4 + 1] = v.y;
            As[r][kq * 4 + 2] = v.z;
            As[r][kq * 4 + 3] = v.w;
        }
        // B tile: 16 x 128 = 512 float4, 2 per thread. Bs[k][h*32+o]
        #pragma unroll
        for (int i = 0; i < 2; i++) {
            int f  = tid + i * 256;
            int k  = f >> 5;
            int jq = f & 31;
            int h  = jq >> 3;
            int o  = (jq & 7) * 4;
            float4 v = *(const float4*)(W + (size_t)h * (DIN * OUTD) +
                                        (size_t)(k0 + k) * OUTD + o);
            *(float4*)(&Bs[k][jq * 4]) = v;
        }
        __syncthreads();

        #pragma unroll
        for (int k = 0; k < GBK; k++) {
            float a[8];
            #pragma unroll
            for (int i = 0; i < 8; i++) a[i] = As[ty * 8 + i][k];
            float4 b0 = *(float4*)(&Bs[k][tx * 8]);
            float4 b1 = *(float4*)(&Bs[k][tx * 8 + 4]);
            float b[8] = {b0.x, b0.y, b0.z, b0.w, b1.x, b1.y, b1.z, b1.w};
            #pragma unroll
            for (int i = 0; i < 8; i++)
                #pragma unroll
                for (int j = 0; j < 8; j++)
                    acc[i][j] = fmaf(a[i], b[j], acc[i][j]);
        }
        __syncthreads();
    }

    #pragma unroll
    for (int i = 0; i < 8; i++) {
        int gr = row0 + ty * 8 + i;
        if (gr < N) {
            float* dst = g_fts + (size_t)gr * JW + tx * 8;
            *(float4*)(dst)     = make_float4(acc[i][0], acc[i][1], acc[i][2], acc[i][3]);
            *(float4*)(dst + 4) = make_float4(acc[i][4], acc[i][5], acc[i][6], acc[i][7]);
        }
    }
}

// ------------------------------------------------------------------
// Kernel 2: per-node attention scalars -> exp tables.
// One warp per node. Lane l: head h=l>>3, quarter q=l&7.
// w_edge = exp(lrelu(f1[r]+f2[c])) = E1*E2 if E1*E2>1 else F1*F2
// where E=exp(f), F=exp(0.2 f). No exp on the edge path.
// ------------------------------------------------------------------
__global__ __launch_bounds__(256) void node_scalars(const float* __restrict__ a1,
                                                    const float* __restrict__ b1,
                                                    const float* __restrict__ a2,
                                                    const float* __restrict__ b2,
                                                    int N) {
    int gw = (blockIdx.x * blockDim.x + threadIdx.x) >> 5;
    if (gw >= N) return;
    int l = threadIdx.x & 31;
    int h = l >> 3;
    int q = l & 7;

    float4 ft  = *(const float4*)(g_fts + (size_t)gw * JW + l * 4);
    float4 a1v = *(const float4*)(a1 + h * OUTD + q * 4);
    float4 a2v = *(const float4*)(a2 + h * OUTD + q * 4);

    float p1 = ft.x * a1v.x + ft.y * a1v.y + ft.z * a1v.z + ft.w * a1v.w;
    float p2 = ft.x * a2v.x + ft.y * a2v.y + ft.z * a2v.z + ft.w * a2v.w;
    #pragma unroll
    for (int m = 4; m >= 1; m >>= 1) {
        p1 += __shfl_xor_sync(0xFFFFFFFFu, p1, m);
        p2 += __shfl_xor_sync(0xFFFFFFFFu, p2, m);
    }
    if (q == 0) {
        float f1 = p1 + b1[h];
        float f2 = p2 + b2[h];
        g_r2[(size_t)gw * HEADS + h] = make_float2(__expf(f1), __expf(ALPHA_LR * f1));
        g_c2[(size_t)gw * HEADS + h] = make_float2(__expf(f2), __expf(ALPHA_LR * f2));
    }
}

// ------------------------------------------------------------------
// CSR construction: histogram -> scan -> scatter
// ------------------------------------------------------------------
__global__ __launch_bounds__(256) void k_hist(const int* __restrict__ er, int E) {
    int e = blockIdx.x * blockDim.x + threadIdx.x;
    if (e < E) atomicAdd(&g_cnt[__ldg(er + e)], 1);
}

// per-1024-block sums
__global__ __launch_bounds__(1024) void k_scan1(int N) {
    __shared__ int sh[32];
    int i = blockIdx.x * 1024 + threadIdx.x;
    int v = (i < N) ? g_cnt[i] : 0;
    #pragma unroll
    for (int m = 16; m >= 1; m >>= 1) v += __shfl_xor_sync(0xFFFFFFFFu, v, m);
    if ((threadIdx.x & 31) == 0) sh[threadIdx.x >> 5] = v;
    __syncthreads();
    if (threadIdx.x < 32) {
        int s = sh[threadIdx.x];
        #pragma unroll
        for (int m = 16; m >= 1; m >>= 1) s += __shfl_xor_sync(0xFFFFFFFFu, s, m);
        if (threadIdx.x == 0) g_part[blockIdx.x] = s;
    }
}

// exclusive scan of block partials (single block)
__global__ __launch_bounds__(128) void k_scan2(int nblk) {
    __shared__ int sh[1024];
    for (int i = threadIdx.x; i < nblk; i += 128) sh[i] = g_part[i];
    __syncthreads();
    if (threadIdx.x == 0) {
        int run = 0;
        for (int j = 0; j < nblk; j++) { int t = sh[j]; sh[j] = run; run += t; }
    }
    __syncthreads();
    for (int i = threadIdx.x; i < nblk; i += 128) g_part[i] = sh[i];
}

// per-element exclusive scan + block offset -> base & cursor
__global__ __launch_bounds__(1024) void k_scan3(int N) {
    __shared__ int wsum[32];
    int i = blockIdx.x * 1024 + threadIdx.x;
    int lane = threadIdx.x & 31;
    int wid  = threadIdx.x >> 5;
    int v = (i < N) ? g_cnt[i] : 0;
    int x = v;
    #pragma unroll
    for (int m = 1; m < 32; m <<= 1) {
        int t = __shfl_up_sync(0xFFFFFFFFu, x, m);
        if (lane >= m) x += t;
    }
    if (lane == 31) wsum[wid] = x;
    __syncthreads();
    if (wid == 0) {
        int y = wsum[lane];
        #pragma unroll
        for (int m = 1; m < 32; m <<= 1) {
            int t = __shfl_up_sync(0xFFFFFFFFu, y, m);
            if (lane >= m) y += t;
        }
        wsum[lane] = y;
    }
    __syncthreads();
    int excl = (x - v) + (wid > 0 ? wsum[wid - 1] : 0);
    int b = g_part[blockIdx.x] + excl;
    if (i < N) { g_base[i] = b; g_cur[i] = b; }
}

__global__ __launch_bounds__(256) void k_scatter(const int* __restrict__ er,
                                                 const int* __restrict__ ec,
                                                 int E) {
    int e = blockIdx.x * blockDim.x + threadIdx.x;
    if (e < E) {
        int r = __ldg(er + e);
        int c = __ldg(ec + e);
        int pos = atomicAdd(&g_cur[r], 1);
        g_scol[pos] = c;
    }
}

// ------------------------------------------------------------------
// Kernel 7: fused aggregation: softmax denom + weighted gather +
// divide + ELU + single write. One warp per node, no atomics.
// ------------------------------------------------------------------
__global__ __launch_bounds__(256) void node_agg(float* __restrict__ out, int N) {
    int gw = (blockIdx.x * blockDim.x + threadIdx.x) >> 5;
    if (gw >= N) return;
    int l = threadIdx.x & 31;
    int h = l >> 3;

    int start = g_base[gw];
    int deg   = g_cnt[gw];
    float2 rr = g_r2[(size_t)gw * HEADS + h];   // {exp(f1), exp(0.2 f1)}

    float4 acc = make_float4(0.f, 0.f, 0.f, 0.f);
    float wsum = 0.f;

    for (int j0 = 0; j0 < deg; j0 += 32) {
        int rem = deg - j0;
        int nch = rem < 32 ? rem : 32;
        int myc = 0;
        if (l < nch) myc = __ldg(g_scol + start + j0 + l);
        for (int jj = 0; jj < nch; jj++) {
            int c = __shfl_sync(0xFFFFFFFFu, myc, jj);
            float2 cc = __ldg(&g_c2[(size_t)c * HEADS + h]); // {exp(f2), exp(0.2 f2)}
            float e12 = rr.x * cc.x;
            float w   = e12 > 1.f ? e12 : rr.y * cc.y;
            float4 ft = *(const float4*)(g_fts + (size_t)c * JW + l * 4);
            acc.x = fmaf(w, ft.x, acc.x);
            acc.y = fmaf(w, ft.y, acc.y);
            acc.z = fmaf(w, ft.z, acc.z);
            acc.w = fmaf(w, ft.w, acc.w);
            wsum += w;
        }
    }

    float inv = wsum > 0.f ? __frcp_rn(wsum) : 0.f;
    float4 v = make_float4(acc.x * inv, acc.y * inv, acc.z * inv, acc.w * inv);
    v.x = v.x > 0.f ? v.x : expm1f(v.x);
    v.y = v.y > 0.f ? v.y : expm1f(v.y);
    v.z = v.z > 0.f ? v.z : expm1f(v.z);
    v.w = v.w > 0.f ? v.w : expm1f(v.w);
    *(float4*)(out + (size_t)gw * JW + l * 4) = v;
}

// ------------------------------------------------------------------
extern "C" void kernel_launch(void* const* d_in, const int* in_sizes, int n_in,
                              void* d_out, int out_size) {
    const float* x  = (const float*)d_in[0];
    const float* W  = (const float*)d_in[1];
    const float* a1 = (const float*)d_in[2];
    const float* b1 = (const float*)d_in[3];
    const float* a2 = (const float*)d_in[4];
    const float* b2 = (const float*)d_in[5];
    const int* er   = (const int*)d_in[6];
    const int* ec   = (const int*)d_in[7];
    float* out      = (float*)d_out;

    const int N = in_sizes[0] / DIN;
    const int E = in_sizes[6];
    const int nblk = (N + 1023) / 1024;

    // zero the degree histogram (memset node is graph-capturable)
    void* cnt_ptr = nullptr;
    cudaGetSymbolAddress(&cnt_ptr, g_cnt);
    cudaMemsetAsync(cnt_ptr, 0, (size_t)N * sizeof(int));

    gemm_fts<<<(N + GBM - 1) / GBM, 256>>>(x, W, N);

    node_scalars<<<((size_t)N * 32 + 255) / 256, 256>>>(a1, b1, a2, b2, N);

    k_hist<<<(E + 255) / 256, 256>>>(er, E);
    k_scan1<<<nblk, 1024>>>(N);
    k_scan2<<<1, 128>>>(nblk);
    k_scan3<<<nblk, 1024>>>(N);
    k_scatter<<<(E + 255) / 256, 256>>>(er, ec, E);

    node_agg<<<((size_t)N * 32 + 255) / 256, 256>>>(out, N);
}